// round 15
// baseline (speedup 1.0000x reference)
#include <cuda_runtime.h>
#include <math.h>
#include <stdint.h>

#define NN 50000
#define EE 400000
#define RR 500
#define XS 100
#define GS 100

static __device__ __constant__ float kNEG = 0.01f;
static __device__ __constant__ float kEPS = 1e-12f;

// ------------------------- scratch (device globals) -------------------------
__device__ float d_xn[NN * XS];
__device__ float d_At[128 * NN];
__device__ float d_Wt[4 * 128 * 128];
__device__ float d_uA[NN * 128];
__device__ float d_vA[NN * 128];
__device__ float d_uB[NN * 128];
__device__ float d_vB[NN * 128];
__device__ float d_accA[NN * 128];
__device__ float d_accB[NN * 128];
__device__ float d_salA[NN * 2];
__device__ float d_salB[NN * 2];
__device__ float d_h[NN * 128];
__device__ float d_ent[NN * 64];
__device__ float d_wA[RR * 128];
__device__ float d_wB[RR * 128];
__device__ float d_psc[NN * 8];
__device__ float d_paw[RR * 4];
__device__ float d_ebS[2 * EE * 2];
__device__ float d_alphaS[2 * EE * 2];
__device__ float d_denA[NN * 2];
__device__ float d_denB[NN * 2];
__device__ int d_counts[2 * NN];
__device__ int d_cur[2 * NN];
__device__ int d_offs[2 * NN];
__device__ int d_csum[256];
__device__ int2 d_edge2[2 * EE];
__device__ int d_posA[EE];
__device__ int d_posB[EE];

// ------------------------- helpers -------------------------
__device__ __forceinline__ float wsum(float v) {
#pragma unroll
    for (int o = 16; o > 0; o >>= 1) v += __shfl_xor_sync(0xffffffffu, v, o);
    return v;
}

__device__ __forceinline__ uint32_t s2u(const void* p) {
    return (uint32_t)__cvta_generic_to_shared(p);
}

// L2-normalize rows of x [NN, XS]
__global__ void norm_x(const float* __restrict__ x, float* __restrict__ xn) {
    int i = blockIdx.x;
    int j = threadIdx.x;
    float v = (j < XS) ? x[i * XS + j] : 0.f;
    float s = wsum(v * v);
    __shared__ float sm[4];
    if ((j & 31) == 0) sm[j >> 5] = s;
    __syncthreads();
    float tot = sm[0] + sm[1] + sm[2] + sm[3];
    if (j < XS) xn[i * XS + j] = v / fmaxf(sqrtf(tot), kEPS);
}

// ------------------------- edge counting sort -------------------------
__global__ void hist_k(const int* __restrict__ rowp, const int* __restrict__ colp,
                       int* __restrict__ counts) {
    int e = blockIdx.x * blockDim.x + threadIdx.x;
    if (e >= EE) return;
    atomicAdd(&counts[colp[e]], 1);
    atomicAdd(&counts[NN + rowp[e]], 1);
}

__global__ void scan1(const int* __restrict__ counts, int* __restrict__ offs,
                      int* __restrict__ csum, int M) {
    __shared__ int sm[512];
    int i = threadIdx.x, g = blockIdx.x * 512 + i;
    int v = (g < M) ? counts[g] : 0;
    sm[i] = v;
    __syncthreads();
    for (int o = 1; o < 512; o <<= 1) {
        int t = (i >= o) ? sm[i - o] : 0;
        __syncthreads();
        sm[i] += t;
        __syncthreads();
    }
    if (g < M) offs[g] = sm[i] - v;
    if (i == 511) csum[blockIdx.x] = sm[511];
}

__global__ void scan2(int* __restrict__ csum, int NB) {
    __shared__ int sm[256];
    int i = threadIdx.x;
    int v = (i < NB) ? csum[i] : 0;
    sm[i] = v;
    __syncthreads();
    for (int o = 1; o < 256; o <<= 1) {
        int t = (i >= o) ? sm[i - o] : 0;
        __syncthreads();
        sm[i] += t;
        __syncthreads();
    }
    if (i < NB) csum[i] = sm[i] - v;
}

__global__ void scan3(int* __restrict__ offs, const int* __restrict__ csum, int M) {
    int g = blockIdx.x * 256 + threadIdx.x;
    if (g < M) offs[g] += csum[g >> 9];
}

__global__ void scatter_k(const int* __restrict__ rowp, const int* __restrict__ colp,
                          const int* __restrict__ et,
                          const int* __restrict__ offs, int* __restrict__ cur,
                          int2* __restrict__ edge2,
                          int* __restrict__ posA, int* __restrict__ posB) {
    int e = blockIdx.x * blockDim.x + threadIdx.x;
    if (e >= EE) return;
    int r = rowp[e], c = colp[e], t = et[e];
    int pA = offs[c] + atomicAdd(&cur[c], 1);
    edge2[pA] = make_int2(r, t);
    posA[e] = pA;
    int pB = offs[NN + r] + atomicAdd(&cur[NN + r], 1);
    edge2[pB] = make_int2(c, t);
    posB[e] = pB;
}

// At[k][m] = A[m][k], zero-padded rows k in [K, 128)
__global__ void transpose_A(const float* __restrict__ A, int M, int K,
                            float* __restrict__ At) {
    __shared__ float t[32][33];
    int mb = blockIdx.x * 32, kb = blockIdx.y * 32;
    int tx = threadIdx.x, ty = threadIdx.y;
#pragma unroll
    for (int i = 0; i < 32; i += 8) {
        int m = mb + ty + i, k = kb + tx;
        t[ty + i][tx] = (m < M && k < K) ? A[(size_t)m * K + k] : 0.f;
    }
    __syncthreads();
#pragma unroll
    for (int i = 0; i < 32; i += 8) {
        int k = kb + ty + i, m = mb + tx;
        if (m < M) At[(size_t)k * M + m] = t[tx][ty + i];
    }
}

// Wt[y][k][n] = Wsel_y[n][koff_y + k], zero-padded
__global__ void prep_wt(const float* __restrict__ Wi, const float* __restrict__ Wo,
                        int ldw, int K, float* __restrict__ Wt) {
    int y = blockIdx.y, k = blockIdx.x, n = threadIdx.x;
    const float* W = (y < 2) ? Wi : Wo;
    int koff = (y & 1) ? K : 0;
    Wt[((y * 128) + k) * 128 + n] = (k < K) ? W[n * ldw + koff + k] : 0.f;
}

// Fused 4-projection GEMM (cp.async 3-stage pipeline) + fused att-dot epilogue.
__global__ __launch_bounds__(256) void gemm4(
    const float* __restrict__ At, int M, int K,
    const float* __restrict__ Wt,
    const float* __restrict__ ai, const float* __restrict__ ao,
    float* __restrict__ uA, float* __restrict__ vA,
    float* __restrict__ uB, float* __restrict__ vB,
    float* __restrict__ psc)
{
    int y = blockIdx.y;
    const float* att = (y < 2) ? ai : ao;
    float* C = (y == 0) ? uA : (y == 1) ? vA : (y == 2) ? uB : vB;
    const float* Wy = Wt + y * 128 * 128;

    __shared__ float As[3][16][128];
    __shared__ float Bs[3][16][128];

    int m0 = blockIdx.x * 128;
    int tid = threadIdx.x;
    int tx = tid & 15;
    int ty = tid >> 4;
    float acc[8][8] = {};

    int KT = (K + 15) / 16;

#define STAGE_TILE(T, BUF)                                                         \
    {                                                                              \
        int k0 = (T) * 16;                                                         \
        uint32_t sA = s2u(&As[BUF][0][0]);                                         \
        uint32_t sB = s2u(&Bs[BUF][0][0]);                                         \
        _Pragma("unroll")                                                          \
        for (int i = 0; i < 2; i++) {                                              \
            int ch = tid + i * 256;                                                \
            int row = ch >> 5;                                                     \
            int coff = (ch & 31) * 4;                                              \
            uint32_t ok = (m0 + coff < M) ? 16u : 0u;                              \
            const float* ga = At + (size_t)(k0 + row) * M + (ok ? (m0 + coff) : 0);\
            asm volatile("cp.async.cg.shared.global [%0], [%1], 16, %2;"           \
                         :: "r"(sA + (uint32_t)((row * 128 + coff) * 4)),          \
                            "l"(ga), "r"(ok));                                     \
            const float* gb = Wy + (k0 + row) * 128 + coff;                        \
            asm volatile("cp.async.cg.shared.global [%0], [%1], 16;"               \
                         :: "r"(sB + (uint32_t)((row * 128 + coff) * 4)),          \
                            "l"(gb));                                              \
        }                                                                          \
        asm volatile("cp.async.commit_group;");                                    \
    }

    STAGE_TILE(0, 0);
    if (KT > 1) STAGE_TILE(1, 1);

    int buf = 0;
    int nbuf = (KT > 2) ? 2 : 0;
    for (int t = 0; t < KT; t++) {
        if (t + 2 < KT) {
            STAGE_TILE(t + 2, nbuf);
            nbuf = (nbuf + 1 == 3) ? 0 : nbuf + 1;
            asm volatile("cp.async.wait_group 2;");
        } else if (t + 1 < KT) {
            asm volatile("cp.async.wait_group 1;");
        } else {
            asm volatile("cp.async.wait_group 0;");
        }
        __syncthreads();
        const float(*Ab)[128] = As[buf];
        const float(*Bb)[128] = Bs[buf];
#pragma unroll
        for (int k = 0; k < 16; k++) {
            float4 a0 = *(const float4*)&Ab[k][ty * 8];
            float4 a1 = *(const float4*)&Ab[k][ty * 8 + 4];
            float4 b0 = *(const float4*)&Bb[k][tx * 8];
            float4 b1 = *(const float4*)&Bb[k][tx * 8 + 4];
            float av[8] = {a0.x, a0.y, a0.z, a0.w, a1.x, a1.y, a1.z, a1.w};
            float bv[8] = {b0.x, b0.y, b0.z, b0.w, b1.x, b1.y, b1.z, b1.w};
#pragma unroll
            for (int i = 0; i < 8; i++)
#pragma unroll
                for (int j = 0; j < 8; j++)
                    acc[i][j] = fmaf(av[i], bv[j], acc[i][j]);
        }
        __syncthreads();
        buf = (buf + 1 == 3) ? 0 : buf + 1;
    }
#undef STAGE_TILE

#pragma unroll
    for (int i = 0; i < 8; i++) {
        int gm = m0 + ty * 8 + i;
        if (gm >= M) continue;
#pragma unroll
        for (int j = 0; j < 8; j += 4) {
            float4 v = make_float4(acc[i][j], acc[i][j + 1], acc[i][j + 2], acc[i][j + 3]);
            *(float4*)&C[(size_t)gm * 128 + tx * 8 + j] = v;
        }
    }

    int h = tx >> 3;
    float attv[8];
#pragma unroll
    for (int j = 0; j < 8; j++) attv[j] = att[tx * 8 + j];
#pragma unroll
    for (int i = 0; i < 8; i++) {
        float pp = 0.f;
#pragma unroll
        for (int j = 0; j < 8; j++) pp = fmaf(attv[j], acc[i][j], pp);
#pragma unroll
        for (int o = 1; o < 8; o <<= 1) pp += __shfl_xor_sync(0xffffffffu, pp, o);
        int gm = m0 + ty * 8 + i;
        if ((tx & 7) == 0 && gm < M)
            atomicAdd(&psc[gm * 8 + y * 2 + h], pp);
    }
}

// C[M x N] = A[M x K] @ W.T (+bias) — entity layer
__global__ __launch_bounds__(256) void gemm_wt(
    const float* __restrict__ A, int lda,
    const float* __restrict__ W, int ldw, int K,
    const float* __restrict__ bias,
    float* __restrict__ C, int ldc, int M)
{
    __shared__ float As[64][17];
    __shared__ float Bs[16][65];
    int m0 = blockIdx.x * 64, n0 = blockIdx.y * 64;
    int tx = threadIdx.x & 15, ty = threadIdx.x >> 4;
    float acc[4][4] = {};
    for (int k0 = 0; k0 < K; k0 += 16) {
#pragma unroll
        for (int i = 0; i < 4; i++) {
            int li = threadIdx.x + i * 256;
            int k = li & 15, m = li >> 4;
            int gm = m0 + m, gk = k0 + k;
            As[m][k] = (gm < M && gk < K) ? A[gm * lda + gk] : 0.f;
        }
#pragma unroll
        for (int i = 0; i < 4; i++) {
            int li = threadIdx.x + i * 256;
            int k = li & 15, n = li >> 4;
            int gk = k0 + k;
            Bs[k][n] = (gk < K) ? W[(n0 + n) * ldw + gk] : 0.f;
        }
        __syncthreads();
#pragma unroll
        for (int k = 0; k < 16; k++) {
            float a[4], b[4];
#pragma unroll
            for (int i = 0; i < 4; i++) a[i] = As[ty * 4 + i][k];
#pragma unroll
            for (int j = 0; j < 4; j++) b[j] = Bs[k][tx * 4 + j];
#pragma unroll
            for (int i = 0; i < 4; i++)
#pragma unroll
                for (int j = 0; j < 4; j++)
                    acc[i][j] = fmaf(a[i], b[j], acc[i][j]);
        }
        __syncthreads();
    }
#pragma unroll
    for (int i = 0; i < 4; i++) {
        int gm = m0 + ty * 4 + i;
        if (gm >= M) continue;
#pragma unroll
        for (int j = 0; j < 4; j++) {
            int gn = n0 + tx * 4 + j;
            C[gm * ldc + gn] = acc[i][j] + bias[gn];
        }
    }
}

// Relation projection for both directions + fused aw reduction (packed output).
__global__ void relproj2(const float* __restrict__ g,
                         const float* __restrict__ Wi, const float* __restrict__ bi,
                         const float* __restrict__ ai,
                         const float* __restrict__ Wo, const float* __restrict__ bo,
                         const float* __restrict__ ao,
                         int ldw, int koff,
                         float* __restrict__ wA, float* __restrict__ wB,
                         float* __restrict__ paw)
{
    int r = blockIdx.x, y = blockIdx.y;
    const float* W = y ? Wo : Wi;
    const float* b = y ? bo : bi;
    const float* att = y ? ao : ai;
    float* wout = y ? wB : wA;
    __shared__ float gs[GS];
    int n = threadIdx.x;
    if (n < GS) gs[n] = g[r * GS + n];
    __syncthreads();
    float acc = b[n];
    const float* wr = W + n * ldw + koff;
#pragma unroll 4
    for (int k = 0; k < GS; k++) acc = fmaf(wr[k], gs[k], acc);
    wout[r * 128 + n] = acc;
    float s = wsum(acc * att[n]);
    __shared__ float sm[4];
    if ((n & 31) == 0) sm[n >> 5] = s;
    __syncthreads();
    if (n == 0) paw[r * 4 + y * 2 + 0] = sm[0] + sm[1];
    if (n == 64) paw[r * 4 + y * 2 + 1] = sm[2] + sm[3];
}

// g_prime: block per relation
__global__ void relproj_out(const float* __restrict__ g, const float* __restrict__ Wr,
                            const float* __restrict__ br, float* __restrict__ out)
{
    int r = blockIdx.x;
    __shared__ float gs[GS];
    int n = threadIdx.x;
    if (n < GS) gs[n] = g[r * GS + n];
    __syncthreads();
    float acc = br[n];
    const float* wr = Wr + n * GS;
#pragma unroll 4
    for (int k = 0; k < GS; k++) acc = fmaf(wr[k], gs[k], acc);
    out[r * 128 + n] = acc;
}

// Fused pass A: one thread per edge; exp values written to SORTED positions.
__global__ __launch_bounds__(256) void pass_a2(
    const int* __restrict__ rowp, const int* __restrict__ colp, const int* __restrict__ et,
    const int* __restrict__ posA, const int* __restrict__ posB,
    const float* __restrict__ psc, const float* __restrict__ paw,
    float* __restrict__ ebS,
    float* __restrict__ denA, float* __restrict__ denB)
{
    int e = blockIdx.x * blockDim.x + threadIdx.x;
    if (e >= EE) return;
    int r = rowp[e], c = colp[e], t = et[e];
    float4 r0 = *(const float4*)&psc[r * 8];
    float4 r1 = *(const float4*)&psc[r * 8 + 4];
    float4 c0 = *(const float4*)&psc[c * 8];
    float4 c1 = *(const float4*)&psc[c * 8 + 4];
    float4 aw = *(const float4*)&paw[t * 4];

    float a0 = r0.x + c0.z + aw.x;
    float a1 = r0.y + c0.w + aw.y;
    float b0 = c1.x + r1.z + aw.z;
    float b1 = c1.y + r1.w + aw.w;

    a0 = (a0 > 0.f) ? a0 : kNEG * a0;
    a1 = (a1 > 0.f) ? a1 : kNEG * a1;
    b0 = (b0 > 0.f) ? b0 : kNEG * b0;
    b1 = (b1 > 0.f) ? b1 : kNEG * b1;
    float ea0 = expf(a0), ea1 = expf(a1), eb0 = expf(b0), eb1 = expf(b1);
    *(float2*)&ebS[(size_t)posA[e] * 2] = make_float2(ea0, ea1);
    *(float2*)&ebS[(size_t)posB[e] * 2] = make_float2(eb0, eb1);
    atomicAdd(&denA[r * 2 + 0], ea0);
    atomicAdd(&denA[r * 2 + 1], ea1);
    atomicAdd(&denB[c * 2 + 0], eb0);
    atomicAdd(&denB[c * 2 + 1], eb1);
}

// Materialize normalized alphas in sorted order (flat, high-MLP).
__global__ __launch_bounds__(256) void alpha_k(
    const int2* __restrict__ edge2, const float* __restrict__ ebS,
    const float* __restrict__ denA, const float* __restrict__ denB,
    float* __restrict__ alphaS)
{
    int p = blockIdx.x * blockDim.x + threadIdx.x;
    if (p >= 2 * EE) return;
    int s = edge2[p].x;
    const float* den = (p < EE) ? denA : denB;
    float2 eb = *(const float2*)&ebS[(size_t)p * 2];
    float2 al;
    al.x = eb.x / den[s * 2 + 0];
    al.y = eb.y / den[s * 2 + 1];
    *(float2*)&alphaS[(size_t)p * 2] = al;
}

// CSR pass B: warp per destination node per direction (combined launch); 4-way unroll.
__global__ __launch_bounds__(256) void pass_b_csr(
    const int2* __restrict__ edge2, const float* __restrict__ alphaS,
    const int* __restrict__ offs, const int* __restrict__ counts,
    const float* __restrict__ uA, const float* __restrict__ wA,
    float* __restrict__ accA, float* __restrict__ salA,
    const float* __restrict__ uB, const float* __restrict__ wB,
    float* __restrict__ accB, float* __restrict__ salB)
{
    int y = blockIdx.y;
    const float* u = y ? uB : uA;
    const float* w = y ? wB : wA;
    float* acc = y ? accB : accA;
    float* sal = y ? salB : salA;

    int d = blockIdx.x * 8 + (threadIdx.x >> 5);
    if (d >= NN) return;
    int l = threadIdx.x & 31;
    int h = l >> 4;
    int slot = y ? NN + d : d;
    int base = offs[slot];
    int cnt = counts[slot];

    float4 a0 = make_float4(0.f, 0.f, 0.f, 0.f);
    float4 a1 = make_float4(0.f, 0.f, 0.f, 0.f);
    float4 a2 = make_float4(0.f, 0.f, 0.f, 0.f);
    float4 a3 = make_float4(0.f, 0.f, 0.f, 0.f);
    float s0 = 0.f, s1 = 0.f, s2 = 0.f, s3 = 0.f;

    int i = 0;
    for (; i + 3 < cnt; i += 4) {
        int2 e0 = edge2[base + i];
        int2 e1 = edge2[base + i + 1];
        int2 e2 = edge2[base + i + 2];
        int2 e3 = edge2[base + i + 3];
        float al0 = alphaS[(size_t)(base + i) * 2 + h];
        float al1 = alphaS[(size_t)(base + i + 1) * 2 + h];
        float al2 = alphaS[(size_t)(base + i + 2) * 2 + h];
        float al3 = alphaS[(size_t)(base + i + 3) * 2 + h];
        float4 u0 = ((const float4*)(u + (size_t)e0.x * 128))[l];
        float4 w0 = ((const float4*)(w + (size_t)e0.y * 128))[l];
        float4 u1 = ((const float4*)(u + (size_t)e1.x * 128))[l];
        float4 w1 = ((const float4*)(w + (size_t)e1.y * 128))[l];
        float4 u2 = ((const float4*)(u + (size_t)e2.x * 128))[l];
        float4 w2 = ((const float4*)(w + (size_t)e2.y * 128))[l];
        float4 u3 = ((const float4*)(u + (size_t)e3.x * 128))[l];
        float4 w3 = ((const float4*)(w + (size_t)e3.y * 128))[l];
        a0.x = fmaf(al0, u0.x + w0.x, a0.x);
        a0.y = fmaf(al0, u0.y + w0.y, a0.y);
        a0.z = fmaf(al0, u0.z + w0.z, a0.z);
        a0.w = fmaf(al0, u0.w + w0.w, a0.w);
        a1.x = fmaf(al1, u1.x + w1.x, a1.x);
        a1.y = fmaf(al1, u1.y + w1.y, a1.y);
        a1.z = fmaf(al1, u1.z + w1.z, a1.z);
        a1.w = fmaf(al1, u1.w + w1.w, a1.w);
        a2.x = fmaf(al2, u2.x + w2.x, a2.x);
        a2.y = fmaf(al2, u2.y + w2.y, a2.y);
        a2.z = fmaf(al2, u2.z + w2.z, a2.z);
        a2.w = fmaf(al2, u2.w + w2.w, a2.w);
        a3.x = fmaf(al3, u3.x + w3.x, a3.x);
        a3.y = fmaf(al3, u3.y + w3.y, a3.y);
        a3.z = fmaf(al3, u3.z + w3.z, a3.z);
        a3.w = fmaf(al3, u3.w + w3.w, a3.w);
        s0 += al0; s1 += al1; s2 += al2; s3 += al3;
    }
    for (; i < cnt; i++) {
        int2 e0 = edge2[base + i];
        float al0 = alphaS[(size_t)(base + i) * 2 + h];
        float4 u0 = ((const float4*)(u + (size_t)e0.x * 128))[l];
        float4 w0 = ((const float4*)(w + (size_t)e0.y * 128))[l];
        a0.x = fmaf(al0, u0.x + w0.x, a0.x);
        a0.y = fmaf(al0, u0.y + w0.y, a0.y);
        a0.z = fmaf(al0, u0.z + w0.z, a0.z);
        a0.w = fmaf(al0, u0.w + w0.w, a0.w);
        s0 += al0;
    }
    a0.x += a1.x + a2.x + a3.x;
    a0.y += a1.y + a2.y + a3.y;
    a0.z += a1.z + a2.z + a3.z;
    a0.w += a1.w + a2.w + a3.w;
    s0 += s1 + s2 + s3;
    *(float4*)&acc[(size_t)d * 128 + l * 4] = a0;
    if (l == 0) sal[d * 2 + 0] = s0;
    if (l == 16) sal[d * 2 + 1] = s0;
}

// out = l2norm_per_head(leaky(0.5*(accA + salA*vA) + 0.5*(accB + salB*vB)))
__global__ void combine(const float* __restrict__ accA, const float* __restrict__ salA,
                        const float* __restrict__ vA,
                        const float* __restrict__ accB, const float* __restrict__ salB,
                        const float* __restrict__ vB,
                        float* __restrict__ out)
{
    int i = blockIdx.x, j = threadIdx.x;
    int h = j >> 6;
    float a = accA[i * 128 + j] + salA[i * 2 + h] * vA[i * 128 + j];
    float b = accB[i * 128 + j] + salB[i * 2 + h] * vB[i * 128 + j];
    float v = 0.5f * (a + b);
    v = (v > 0.f) ? v : kNEG * v;
    float s = wsum(v * v);
    __shared__ float sm[4];
    if ((j & 31) == 0) sm[j >> 5] = s;
    __syncthreads();
    float tot = sm[h * 2] + sm[h * 2 + 1];
    out[i * 128 + j] = v / fmaxf(sqrtf(tot), kEPS);
}

// Layer-2 fused epilogue: per-head norm of combined h, add ent, full-128 norm.
__global__ void combine_final(
    const float* __restrict__ accA, const float* __restrict__ salA,
    const float* __restrict__ vA,
    const float* __restrict__ accB, const float* __restrict__ salB,
    const float* __restrict__ vB,
    const float* __restrict__ ent,
    float* __restrict__ out)
{
    int i = blockIdx.x, j = threadIdx.x;
    int h = j >> 6;
    float a = accA[i * 128 + j] + salA[i * 2 + h] * vA[i * 128 + j];
    float b = accB[i * 128 + j] + salB[i * 2 + h] * vB[i * 128 + j];
    float v = 0.5f * (a + b);
    v = (v > 0.f) ? v : kNEG * v;
    float s = wsum(v * v);
    __shared__ float sm[4];
    if ((j & 31) == 0) sm[j >> 5] = s;
    __syncthreads();
    float tot = sm[h * 2] + sm[h * 2 + 1];
    float hval = v / fmaxf(sqrtf(tot), kEPS);
    // entity add + full-128 l2norm
    float t2 = ent[i * 64 + (j & 63)] + hval;
    float s2 = wsum(t2 * t2);
    __shared__ float sm2[4];
    if ((j & 31) == 0) sm2[j >> 5] = s2;
    __syncthreads();
    float tot2 = sm2[0] + sm2[1] + sm2[2] + sm2[3];
    out[i * 128 + j] = t2 / fmaxf(sqrtf(tot2), kEPS);
}

// ------------------------- host orchestration -------------------------
namespace {
struct Ptrs {
    float *xn, *At, *Wt, *uA, *vA, *uB, *vB, *accA, *accB, *salA, *salB, *h, *ent, *wA, *wB;
    float *psc, *paw, *ebS, *alphaS, *denA, *denB;
    int *counts, *cur, *offs, *csum, *posA, *posB;
    int2 *edge2;
};

static void get_ptrs(Ptrs& p) {
    cudaGetSymbolAddress((void**)&p.xn, d_xn);
    cudaGetSymbolAddress((void**)&p.At, d_At);
    cudaGetSymbolAddress((void**)&p.Wt, d_Wt);
    cudaGetSymbolAddress((void**)&p.uA, d_uA);
    cudaGetSymbolAddress((void**)&p.vA, d_vA);
    cudaGetSymbolAddress((void**)&p.uB, d_uB);
    cudaGetSymbolAddress((void**)&p.vB, d_vB);
    cudaGetSymbolAddress((void**)&p.accA, d_accA);
    cudaGetSymbolAddress((void**)&p.accB, d_accB);
    cudaGetSymbolAddress((void**)&p.salA, d_salA);
    cudaGetSymbolAddress((void**)&p.salB, d_salB);
    cudaGetSymbolAddress((void**)&p.h, d_h);
    cudaGetSymbolAddress((void**)&p.ent, d_ent);
    cudaGetSymbolAddress((void**)&p.wA, d_wA);
    cudaGetSymbolAddress((void**)&p.wB, d_wB);
    cudaGetSymbolAddress((void**)&p.psc, d_psc);
    cudaGetSymbolAddress((void**)&p.paw, d_paw);
    cudaGetSymbolAddress((void**)&p.ebS, d_ebS);
    cudaGetSymbolAddress((void**)&p.alphaS, d_alphaS);
    cudaGetSymbolAddress((void**)&p.denA, d_denA);
    cudaGetSymbolAddress((void**)&p.denB, d_denB);
    cudaGetSymbolAddress((void**)&p.counts, d_counts);
    cudaGetSymbolAddress((void**)&p.cur, d_cur);
    cudaGetSymbolAddress((void**)&p.offs, d_offs);
    cudaGetSymbolAddress((void**)&p.csum, d_csum);
    cudaGetSymbolAddress((void**)&p.posA, d_posA);
    cudaGetSymbolAddress((void**)&p.posB, d_posB);
    cudaGetSymbolAddress((void**)&p.edge2, d_edge2);
}

// Runs everything for one layer up to (but excluding) the combine epilogue.
static void run_layer_core(const Ptrs& p,
                           const float* A, int K, int ldw,
                           const float* Wi, const float* bi, const float* ai,
                           const float* Wo, const float* bo, const float* ao,
                           const float* g,
                           const int* rowp, const int* colp, const int* et)
{
    transpose_A<<<dim3((NN + 31) / 32, 4), dim3(32, 8)>>>(A, NN, K, p.At);
    prep_wt<<<dim3(128, 4), 128>>>(Wi, Wo, ldw, K, p.Wt);
    cudaMemsetAsync(p.psc, 0, NN * 8 * sizeof(float));
    dim3 gg((NN + 127) / 128, 4);
    gemm4<<<gg, 256>>>(p.At, NN, K, p.Wt, ai, ao,
                       p.uA, p.vA, p.uB, p.vB, p.psc);
    dim3 gr(RR, 2);
    relproj2<<<gr, 128>>>(g, Wi, bi, ai, Wo, bo, ao, ldw, 2 * K,
                          p.wA, p.wB, p.paw);
    cudaMemsetAsync(p.denA, 0, NN * 2 * sizeof(float));
    cudaMemsetAsync(p.denB, 0, NN * 2 * sizeof(float));
    pass_a2<<<(EE + 255) / 256, 256>>>(rowp, colp, et, p.posA, p.posB,
                                       p.psc, p.paw, p.ebS, p.denA, p.denB);
    alpha_k<<<(2 * EE + 255) / 256, 256>>>(p.edge2, p.ebS, p.denA, p.denB, p.alphaS);
    dim3 gb((NN + 7) / 8, 2);
    pass_b_csr<<<gb, 256>>>(p.edge2, p.alphaS, p.offs, p.counts,
                            p.uA, p.wA, p.accA, p.salA,
                            p.uB, p.wB, p.accB, p.salB);
}
}  // namespace

extern "C" void kernel_launch(void* const* d_in, const int* in_sizes, int n_in,
                              void* d_out, int out_size)
{
    const float* x   = (const float*)d_in[0];
    const float* g   = (const float*)d_in[1];
    const int*   ei  = (const int*)d_in[2];
    const int*   et  = (const int*)d_in[3];
    const float* W1i = (const float*)d_in[4];
    const float* b1i = (const float*)d_in[5];
    const float* a1i = (const float*)d_in[6];
    const float* W1o = (const float*)d_in[7];
    const float* b1o = (const float*)d_in[8];
    const float* a1o = (const float*)d_in[9];
    const float* W2i = (const float*)d_in[10];
    const float* b2i = (const float*)d_in[11];
    const float* a2i = (const float*)d_in[12];
    const float* W2o = (const float*)d_in[13];
    const float* b2o = (const float*)d_in[14];
    const float* a2o = (const float*)d_in[15];
    const float* We  = (const float*)d_in[16];
    const float* be  = (const float*)d_in[17];
    const float* Wr  = (const float*)d_in[18];
    const float* br  = (const float*)d_in[19];
    float* out = (float*)d_out;

    const int* rowp = ei;
    const int* colp = ei + EE;

    Ptrs p;
    get_ptrs(p);

    // edge counting sort (once per call; shared by both layers & directions)
    const int M2 = 2 * NN;
    const int NB = (M2 + 511) / 512;
    cudaMemsetAsync(p.counts, 0, M2 * sizeof(int));
    cudaMemsetAsync(p.cur, 0, M2 * sizeof(int));
    hist_k<<<(EE + 255) / 256, 256>>>(rowp, colp, p.counts);
    scan1<<<NB, 512>>>(p.counts, p.offs, p.csum, M2);
    scan2<<<1, 256>>>(p.csum, NB);
    scan3<<<(M2 + 255) / 256, 256>>>(p.offs, p.csum, M2);
    scatter_k<<<(EE + 255) / 256, 256>>>(rowp, colp, et, p.offs, p.cur,
                                         p.edge2, p.posA, p.posB);

    norm_x<<<NN, 128>>>(x, p.xn);

    // entity layer early (depends only on xn)
    dim3 ge((NN + 63) / 64, 1);
    gemm_wt<<<ge, 256>>>(p.xn, XS, We, XS, XS, be, p.ent, 64, NN);

    // layer 1: input xn [NN,100]
    run_layer_core(p, p.xn, XS, 2 * XS + GS,
                   W1i, b1i, a1i, W1o, b1o, a1o, g, rowp, colp, et);
    combine<<<NN, 128>>>(p.accA, p.salA, p.vA, p.accB, p.salB, p.vB, p.h);

    // layer 2: input h [NN,128]; epilogue fused with entity add + final norm
    run_layer_core(p, p.h, 128, 2 * 128 + GS,
                   W2i, b2i, a2i, W2o, b2o, a2o, g, rowp, colp, et);
    combine_final<<<NN, 128>>>(p.accA, p.salA, p.vA, p.accB, p.salB, p.vB,
                               p.ent, out);

    // g_prime -> out[NN*128 : NN*128 + RR*128)
    relproj_out<<<RR, 128>>>(g, Wr, br, out + NN * 128);
}

// round 16
// speedup vs baseline: 1.0447x; 1.0447x over previous
#include <cuda_runtime.h>
#include <math.h>
#include <stdint.h>

#define NN 50000
#define EE 400000
#define RR 500
#define XS 100
#define GS 100

static __device__ __constant__ float kNEG = 0.01f;
static __device__ __constant__ float kEPS = 1e-12f;

// ------------------------- scratch (device globals) -------------------------
__device__ float d_xn[NN * XS];
__device__ float d_At[128 * NN];        // k-major transposed activations (zero-padded)
__device__ float d_Wt[4 * 128 * 128];   // k-major weight slices per projection y
__device__ float d_uA[NN * 128];
__device__ float d_vA[NN * 128];
__device__ float d_uB[NN * 128];
__device__ float d_vB[NN * 128];
__device__ float d_accA[NN * 128];
__device__ float d_accB[NN * 128];
__device__ float d_salA[NN * 2];
__device__ float d_salB[NN * 2];
__device__ float d_h[NN * 128];
__device__ float d_ent[NN * 64];
__device__ float d_wA[RR * 128];
__device__ float d_wB[RR * 128];
__device__ float d_psc[NN * 8];
__device__ float d_paw[RR * 4];
__device__ float d_ebS[2 * EE * 2];     // exp values in SORTED order (dirA:[0,EE), dirB:[EE,2EE))
__device__ float d_alphaS[2 * EE * 2];  // normalized alphas in sorted order
__device__ float d_denA[NN * 2];
__device__ float d_denB[NN * 2];
// edge sort scratch: [0,NN) = counts by col (dirA dest), [NN,2NN) by row (dirB dest)
__device__ int d_counts[2 * NN];
__device__ int d_cur[2 * NN];
__device__ int d_offs[2 * NN];
__device__ int d_csum[256];
__device__ int2 d_edge2[2 * EE];        // sorted edge payload: {src, type}
__device__ int d_posA[EE];
__device__ int d_posB[EE];

// ------------------------- helpers -------------------------
__device__ __forceinline__ float wsum(float v) {
#pragma unroll
    for (int o = 16; o > 0; o >>= 1) v += __shfl_xor_sync(0xffffffffu, v, o);
    return v;
}

__device__ __forceinline__ uint32_t s2u(const void* p) {
    return (uint32_t)__cvta_generic_to_shared(p);
}

// L2-normalize rows of x [NN, XS]
__global__ void norm_x(const float* __restrict__ x, float* __restrict__ xn) {
    int i = blockIdx.x;
    int j = threadIdx.x;
    float v = (j < XS) ? x[i * XS + j] : 0.f;
    float s = wsum(v * v);
    __shared__ float sm[4];
    if ((j & 31) == 0) sm[j >> 5] = s;
    __syncthreads();
    float tot = sm[0] + sm[1] + sm[2] + sm[3];
    if (j < XS) xn[i * XS + j] = v / fmaxf(sqrtf(tot), kEPS);
}

// ------------------------- edge counting sort -------------------------
__global__ void hist_k(const int* __restrict__ rowp, const int* __restrict__ colp,
                       int* __restrict__ counts) {
    int e = blockIdx.x * blockDim.x + threadIdx.x;
    if (e >= EE) return;
    atomicAdd(&counts[colp[e]], 1);
    atomicAdd(&counts[NN + rowp[e]], 1);
}

__global__ void scan1(const int* __restrict__ counts, int* __restrict__ offs,
                      int* __restrict__ csum, int M) {
    __shared__ int sm[512];
    int i = threadIdx.x, g = blockIdx.x * 512 + i;
    int v = (g < M) ? counts[g] : 0;
    sm[i] = v;
    __syncthreads();
    for (int o = 1; o < 512; o <<= 1) {
        int t = (i >= o) ? sm[i - o] : 0;
        __syncthreads();
        sm[i] += t;
        __syncthreads();
    }
    if (g < M) offs[g] = sm[i] - v;
    if (i == 511) csum[blockIdx.x] = sm[511];
}

__global__ void scan2(int* __restrict__ csum, int NB) {
    __shared__ int sm[256];
    int i = threadIdx.x;
    int v = (i < NB) ? csum[i] : 0;
    sm[i] = v;
    __syncthreads();
    for (int o = 1; o < 256; o <<= 1) {
        int t = (i >= o) ? sm[i - o] : 0;
        __syncthreads();
        sm[i] += t;
        __syncthreads();
    }
    if (i < NB) csum[i] = sm[i] - v;
}

__global__ void scan3(int* __restrict__ offs, const int* __restrict__ csum, int M) {
    int g = blockIdx.x * 256 + threadIdx.x;
    if (g < M) offs[g] += csum[g >> 9];
}

__global__ void scatter_k(const int* __restrict__ rowp, const int* __restrict__ colp,
                          const int* __restrict__ et,
                          const int* __restrict__ offs, int* __restrict__ cur,
                          int2* __restrict__ edge2,
                          int* __restrict__ posA, int* __restrict__ posB) {
    int e = blockIdx.x * blockDim.x + threadIdx.x;
    if (e >= EE) return;
    int r = rowp[e], c = colp[e], t = et[e];
    int pA = offs[c] + atomicAdd(&cur[c], 1);
    edge2[pA] = make_int2(r, t);               // dirA: dest=col, src=row
    posA[e] = pA;
    int pB = offs[NN + r] + atomicAdd(&cur[NN + r], 1);   // pB in [EE, 2EE)
    edge2[pB] = make_int2(c, t);               // dirB: dest=row, src=col
    posB[e] = pB;
}

// At[k][m] = A[m][k], zero-padded rows k in [K, 128)
__global__ void transpose_A(const float* __restrict__ A, int M, int K,
                            float* __restrict__ At) {
    __shared__ float t[32][33];
    int mb = blockIdx.x * 32, kb = blockIdx.y * 32;
    int tx = threadIdx.x, ty = threadIdx.y;
#pragma unroll
    for (int i = 0; i < 32; i += 8) {
        int m = mb + ty + i, k = kb + tx;
        t[ty + i][tx] = (m < M && k < K) ? A[(size_t)m * K + k] : 0.f;
    }
    __syncthreads();
#pragma unroll
    for (int i = 0; i < 32; i += 8) {
        int k = kb + ty + i, m = mb + tx;
        if (m < M) At[(size_t)k * M + m] = t[tx][ty + i];
    }
}

// Wt[y][k][n] = Wsel_y[n][koff_y + k], zero-padded
__global__ void prep_wt(const float* __restrict__ Wi, const float* __restrict__ Wo,
                        int ldw, int K, float* __restrict__ Wt) {
    int y = blockIdx.y, k = blockIdx.x, n = threadIdx.x;
    const float* W = (y < 2) ? Wi : Wo;
    int koff = (y & 1) ? K : 0;
    Wt[((y * 128) + k) * 128 + n] = (k < K) ? W[n * ldw + koff + k] : 0.f;
}

// Fused 4-projection GEMM (cp.async double-buffered) + fused att-dot epilogue.
__global__ __launch_bounds__(256) void gemm4(
    const float* __restrict__ At, int M, int K,
    const float* __restrict__ Wt,
    const float* __restrict__ ai, const float* __restrict__ ao,
    float* __restrict__ uA, float* __restrict__ vA,
    float* __restrict__ uB, float* __restrict__ vB,
    float* __restrict__ psc)
{
    int y = blockIdx.y;
    const float* att = (y < 2) ? ai : ao;
    float* C = (y == 0) ? uA : (y == 1) ? vA : (y == 2) ? uB : vB;
    const float* Wy = Wt + y * 128 * 128;

    __shared__ float As[2][16][128];
    __shared__ float Bs[2][16][128];

    int m0 = blockIdx.x * 128;
    int tid = threadIdx.x;
    int tx = tid & 15;
    int ty = tid >> 4;
    float acc[8][8] = {};

    int KT = (K + 15) / 16;

#define STAGE_TILE(T, BUF)                                                         \
    {                                                                              \
        int k0 = (T) * 16;                                                         \
        uint32_t sA = s2u(&As[BUF][0][0]);                                         \
        uint32_t sB = s2u(&Bs[BUF][0][0]);                                         \
        _Pragma("unroll")                                                          \
        for (int i = 0; i < 2; i++) {                                              \
            int ch = tid + i * 256;                                                \
            int row = ch >> 5;                                                     \
            int coff = (ch & 31) * 4;                                              \
            uint32_t ok = (m0 + coff < M) ? 16u : 0u;                              \
            const float* ga = At + (size_t)(k0 + row) * M + (ok ? (m0 + coff) : 0);\
            asm volatile("cp.async.cg.shared.global [%0], [%1], 16, %2;"           \
                         :: "r"(sA + (uint32_t)((row * 128 + coff) * 4)),          \
                            "l"(ga), "r"(ok));                                     \
            const float* gb = Wy + (k0 + row) * 128 + coff;                        \
            asm volatile("cp.async.cg.shared.global [%0], [%1], 16;"               \
                         :: "r"(sB + (uint32_t)((row * 128 + coff) * 4)),          \
                            "l"(gb));                                              \
        }                                                                          \
        asm volatile("cp.async.commit_group;");                                    \
    }

    STAGE_TILE(0, 0);

    for (int t = 0; t < KT; t++) {
        int buf = t & 1;
        if (t + 1 < KT) {
            STAGE_TILE(t + 1, buf ^ 1);
            asm volatile("cp.async.wait_group 1;");
        } else {
            asm volatile("cp.async.wait_group 0;");
        }
        __syncthreads();
        const float(*Ab)[128] = As[buf];
        const float(*Bb)[128] = Bs[buf];
#pragma unroll
        for (int k = 0; k < 16; k++) {
            float4 a0 = *(const float4*)&Ab[k][ty * 8];
            float4 a1 = *(const float4*)&Ab[k][ty * 8 + 4];
            float4 b0 = *(const float4*)&Bb[k][tx * 8];
            float4 b1 = *(const float4*)&Bb[k][tx * 8 + 4];
            float av[8] = {a0.x, a0.y, a0.z, a0.w, a1.x, a1.y, a1.z, a1.w};
            float bv[8] = {b0.x, b0.y, b0.z, b0.w, b1.x, b1.y, b1.z, b1.w};
#pragma unroll
            for (int i = 0; i < 8; i++)
#pragma unroll
                for (int j = 0; j < 8; j++)
                    acc[i][j] = fmaf(av[i], bv[j], acc[i][j]);
        }
        __syncthreads();
    }
#undef STAGE_TILE

#pragma unroll
    for (int i = 0; i < 8; i++) {
        int gm = m0 + ty * 8 + i;
        if (gm >= M) continue;
#pragma unroll
        for (int j = 0; j < 8; j += 4) {
            float4 v = make_float4(acc[i][j], acc[i][j + 1], acc[i][j + 2], acc[i][j + 3]);
            *(float4*)&C[(size_t)gm * 128 + tx * 8 + j] = v;
        }
    }

    int h = tx >> 3;
    float attv[8];
#pragma unroll
    for (int j = 0; j < 8; j++) attv[j] = att[tx * 8 + j];
#pragma unroll
    for (int i = 0; i < 8; i++) {
        float pp = 0.f;
#pragma unroll
        for (int j = 0; j < 8; j++) pp = fmaf(attv[j], acc[i][j], pp);
#pragma unroll
        for (int o = 1; o < 8; o <<= 1) pp += __shfl_xor_sync(0xffffffffu, pp, o);
        int gm = m0 + ty * 8 + i;
        if ((tx & 7) == 0 && gm < M)
            atomicAdd(&psc[gm * 8 + y * 2 + h], pp);
    }
}

// C[M x N] = A[M x K] @ W.T (+bias) — entity layer
__global__ __launch_bounds__(256) void gemm_wt(
    const float* __restrict__ A, int lda,
    const float* __restrict__ W, int ldw, int K,
    const float* __restrict__ bias,
    float* __restrict__ C, int ldc, int M)
{
    __shared__ float As[64][17];
    __shared__ float Bs[16][65];
    int m0 = blockIdx.x * 64, n0 = blockIdx.y * 64;
    int tx = threadIdx.x & 15, ty = threadIdx.x >> 4;
    float acc[4][4] = {};
    for (int k0 = 0; k0 < K; k0 += 16) {
#pragma unroll
        for (int i = 0; i < 4; i++) {
            int li = threadIdx.x + i * 256;
            int k = li & 15, m = li >> 4;
            int gm = m0 + m, gk = k0 + k;
            As[m][k] = (gm < M && gk < K) ? A[gm * lda + gk] : 0.f;
        }
#pragma unroll
        for (int i = 0; i < 4; i++) {
            int li = threadIdx.x + i * 256;
            int k = li & 15, n = li >> 4;
            int gk = k0 + k;
            Bs[k][n] = (gk < K) ? W[(n0 + n) * ldw + gk] : 0.f;
        }
        __syncthreads();
#pragma unroll
        for (int k = 0; k < 16; k++) {
            float a[4], b[4];
#pragma unroll
            for (int i = 0; i < 4; i++) a[i] = As[ty * 4 + i][k];
#pragma unroll
            for (int j = 0; j < 4; j++) b[j] = Bs[k][tx * 4 + j];
#pragma unroll
            for (int i = 0; i < 4; i++)
#pragma unroll
                for (int j = 0; j < 4; j++)
                    acc[i][j] = fmaf(a[i], b[j], acc[i][j]);
        }
        __syncthreads();
    }
#pragma unroll
    for (int i = 0; i < 4; i++) {
        int gm = m0 + ty * 4 + i;
        if (gm >= M) continue;
#pragma unroll
        for (int j = 0; j < 4; j++) {
            int gn = n0 + tx * 4 + j;
            C[gm * ldc + gn] = acc[i][j] + bias[gn];
        }
    }
}

// Relation projection for both directions + fused aw reduction (packed output).
__global__ void relproj2(const float* __restrict__ g,
                         const float* __restrict__ Wi, const float* __restrict__ bi,
                         const float* __restrict__ ai,
                         const float* __restrict__ Wo, const float* __restrict__ bo,
                         const float* __restrict__ ao,
                         int ldw, int koff,
                         float* __restrict__ wA, float* __restrict__ wB,
                         float* __restrict__ paw)
{
    int r = blockIdx.x, y = blockIdx.y;
    const float* W = y ? Wo : Wi;
    const float* b = y ? bo : bi;
    const float* att = y ? ao : ai;
    float* wout = y ? wB : wA;
    __shared__ float gs[GS];
    int n = threadIdx.x;
    if (n < GS) gs[n] = g[r * GS + n];
    __syncthreads();
    float acc = b[n];
    const float* wr = W + n * ldw + koff;
#pragma unroll 4
    for (int k = 0; k < GS; k++) acc = fmaf(wr[k], gs[k], acc);
    wout[r * 128 + n] = acc;
    float s = wsum(acc * att[n]);
    __shared__ float sm[4];
    if ((n & 31) == 0) sm[n >> 5] = s;
    __syncthreads();
    if (n == 0) paw[r * 4 + y * 2 + 0] = sm[0] + sm[1];
    if (n == 64) paw[r * 4 + y * 2 + 1] = sm[2] + sm[3];
}

// g_prime: block per relation
__global__ void relproj_out(const float* __restrict__ g, const float* __restrict__ Wr,
                            const float* __restrict__ br, float* __restrict__ out)
{
    int r = blockIdx.x;
    __shared__ float gs[GS];
    int n = threadIdx.x;
    if (n < GS) gs[n] = g[r * GS + n];
    __syncthreads();
    float acc = br[n];
    const float* wr = Wr + n * GS;
#pragma unroll 4
    for (int k = 0; k < GS; k++) acc = fmaf(wr[k], gs[k], acc);
    out[r * 128 + n] = acc;
}

// Fused pass A: one thread per edge; exp values written to SORTED positions.
__global__ __launch_bounds__(256) void pass_a2(
    const int* __restrict__ rowp, const int* __restrict__ colp, const int* __restrict__ et,
    const int* __restrict__ posA, const int* __restrict__ posB,
    const float* __restrict__ psc, const float* __restrict__ paw,
    float* __restrict__ ebS,
    float* __restrict__ denA, float* __restrict__ denB)
{
    int e = blockIdx.x * blockDim.x + threadIdx.x;
    if (e >= EE) return;
    int r = rowp[e], c = colp[e], t = et[e];
    float4 r0 = *(const float4*)&psc[r * 8];
    float4 r1 = *(const float4*)&psc[r * 8 + 4];
    float4 c0 = *(const float4*)&psc[c * 8];
    float4 c1 = *(const float4*)&psc[c * 8 + 4];
    float4 aw = *(const float4*)&paw[t * 4];

    float a0 = r0.x + c0.z + aw.x;
    float a1 = r0.y + c0.w + aw.y;
    float b0 = c1.x + r1.z + aw.z;
    float b1 = c1.y + r1.w + aw.w;

    a0 = (a0 > 0.f) ? a0 : kNEG * a0;
    a1 = (a1 > 0.f) ? a1 : kNEG * a1;
    b0 = (b0 > 0.f) ? b0 : kNEG * b0;
    b1 = (b1 > 0.f) ? b1 : kNEG * b1;
    float ea0 = expf(a0), ea1 = expf(a1), eb0 = expf(b0), eb1 = expf(b1);
    *(float2*)&ebS[(size_t)posA[e] * 2] = make_float2(ea0, ea1);
    *(float2*)&ebS[(size_t)posB[e] * 2] = make_float2(eb0, eb1);
    atomicAdd(&denA[r * 2 + 0], ea0);
    atomicAdd(&denA[r * 2 + 1], ea1);
    atomicAdd(&denB[c * 2 + 0], eb0);
    atomicAdd(&denB[c * 2 + 1], eb1);
}

// Materialize normalized alphas in sorted order (flat, high-MLP).
__global__ __launch_bounds__(256) void alpha_k(
    const int2* __restrict__ edge2, const float* __restrict__ ebS,
    const float* __restrict__ denA, const float* __restrict__ denB,
    float* __restrict__ alphaS)
{
    int p = blockIdx.x * blockDim.x + threadIdx.x;
    if (p >= 2 * EE) return;
    int s = edge2[p].x;
    const float* den = (p < EE) ? denA : denB;
    float2 eb = *(const float2*)&ebS[(size_t)p * 2];
    float2 al;
    al.x = eb.x / den[s * 2 + 0];
    al.y = eb.y / den[s * 2 + 1];
    *(float2*)&alphaS[(size_t)p * 2] = al;
}

// CSR pass B: warp per destination node per direction; 2-way unrolled chain.
__global__ __launch_bounds__(256) void pass_b_csr(
    const int2* __restrict__ edge2, const float* __restrict__ alphaS,
    const int* __restrict__ offs, const int* __restrict__ counts,
    const float* __restrict__ uA, const float* __restrict__ wA,
    float* __restrict__ accA, float* __restrict__ salA,
    const float* __restrict__ uB, const float* __restrict__ wB,
    float* __restrict__ accB, float* __restrict__ salB)
{
    int y = blockIdx.y;
    const float* u = y ? uB : uA;
    const float* w = y ? wB : wA;
    float* acc = y ? accB : accA;
    float* sal = y ? salB : salA;

    int d = blockIdx.x * 8 + (threadIdx.x >> 5);
    if (d >= NN) return;
    int l = threadIdx.x & 31;
    int h = l >> 4;
    int slot = y ? NN + d : d;
    int base = offs[slot];
    int cnt = counts[slot];

    float4 a0 = make_float4(0.f, 0.f, 0.f, 0.f);
    float4 a1 = make_float4(0.f, 0.f, 0.f, 0.f);
    float s0 = 0.f, s1 = 0.f;

    int i = 0;
    for (; i + 1 < cnt; i += 2) {
        int2 eA = edge2[base + i];
        int2 eB = edge2[base + i + 1];
        float alA = alphaS[(size_t)(base + i) * 2 + h];
        float alB = alphaS[(size_t)(base + i + 1) * 2 + h];
        float4 u0 = ((const float4*)(u + (size_t)eA.x * 128))[l];
        float4 w0 = ((const float4*)(w + (size_t)eA.y * 128))[l];
        float4 u1 = ((const float4*)(u + (size_t)eB.x * 128))[l];
        float4 w1 = ((const float4*)(w + (size_t)eB.y * 128))[l];
        a0.x = fmaf(alA, u0.x + w0.x, a0.x);
        a0.y = fmaf(alA, u0.y + w0.y, a0.y);
        a0.z = fmaf(alA, u0.z + w0.z, a0.z);
        a0.w = fmaf(alA, u0.w + w0.w, a0.w);
        a1.x = fmaf(alB, u1.x + w1.x, a1.x);
        a1.y = fmaf(alB, u1.y + w1.y, a1.y);
        a1.z = fmaf(alB, u1.z + w1.z, a1.z);
        a1.w = fmaf(alB, u1.w + w1.w, a1.w);
        s0 += alA;
        s1 += alB;
    }
    if (i < cnt) {
        int2 eA = edge2[base + i];
        float alA = alphaS[(size_t)(base + i) * 2 + h];
        float4 u0 = ((const float4*)(u + (size_t)eA.x * 128))[l];
        float4 w0 = ((const float4*)(w + (size_t)eA.y * 128))[l];
        a0.x = fmaf(alA, u0.x + w0.x, a0.x);
        a0.y = fmaf(alA, u0.y + w0.y, a0.y);
        a0.z = fmaf(alA, u0.z + w0.z, a0.z);
        a0.w = fmaf(alA, u0.w + w0.w, a0.w);
        s0 += alA;
    }
    a0.x += a1.x; a0.y += a1.y; a0.z += a1.z; a0.w += a1.w;
    s0 += s1;
    *(float4*)&acc[(size_t)d * 128 + l * 4] = a0;
    if (l == 0) sal[d * 2 + 0] = s0;
    if (l == 16) sal[d * 2 + 1] = s0;
}

// out = l2norm_per_head(leaky(0.5*(accA + salA*vA) + 0.5*(accB + salB*vB)))
__global__ void combine(const float* __restrict__ accA, const float* __restrict__ salA,
                        const float* __restrict__ vA,
                        const float* __restrict__ accB, const float* __restrict__ salB,
                        const float* __restrict__ vB,
                        float* __restrict__ out)
{
    int i = blockIdx.x, j = threadIdx.x;
    int h = j >> 6;
    float a = accA[i * 128 + j] + salA[i * 2 + h] * vA[i * 128 + j];
    float b = accB[i * 128 + j] + salB[i * 2 + h] * vB[i * 128 + j];
    float v = 0.5f * (a + b);
    v = (v > 0.f) ? v : kNEG * v;
    float s = wsum(v * v);
    __shared__ float sm[4];
    if ((j & 31) == 0) sm[j >> 5] = s;
    __syncthreads();
    float tot = sm[h * 2] + sm[h * 2 + 1];
    out[i * 128 + j] = v / fmaxf(sqrtf(tot), kEPS);
}

// Layer-2 fused epilogue: per-head norm of combined h, add ent, full-128 norm.
__global__ void combine_final(
    const float* __restrict__ accA, const float* __restrict__ salA,
    const float* __restrict__ vA,
    const float* __restrict__ accB, const float* __restrict__ salB,
    const float* __restrict__ vB,
    const float* __restrict__ ent,
    float* __restrict__ out)
{
    int i = blockIdx.x, j = threadIdx.x;
    int h = j >> 6;
    float a = accA[i * 128 + j] + salA[i * 2 + h] * vA[i * 128 + j];
    float b = accB[i * 128 + j] + salB[i * 2 + h] * vB[i * 128 + j];
    float v = 0.5f * (a + b);
    v = (v > 0.f) ? v : kNEG * v;
    float s = wsum(v * v);
    __shared__ float sm[4];
    if ((j & 31) == 0) sm[j >> 5] = s;
    __syncthreads();
    float tot = sm[h * 2] + sm[h * 2 + 1];
    float hval = v / fmaxf(sqrtf(tot), kEPS);
    float t2 = ent[i * 64 + (j & 63)] + hval;
    float s2 = wsum(t2 * t2);
    __shared__ float sm2[4];
    if ((j & 31) == 0) sm2[j >> 5] = s2;
    __syncthreads();
    float tot2 = sm2[0] + sm2[1] + sm2[2] + sm2[3];
    out[i * 128 + j] = t2 / fmaxf(sqrtf(tot2), kEPS);
}

// ------------------------- host orchestration -------------------------
namespace {
struct Ptrs {
    float *xn, *At, *Wt, *uA, *vA, *uB, *vB, *accA, *accB, *salA, *salB, *h, *ent, *wA, *wB;
    float *psc, *paw, *ebS, *alphaS, *denA, *denB;
    int *counts, *cur, *offs, *csum, *posA, *posB;
    int2 *edge2;
};

static void get_ptrs(Ptrs& p) {
    cudaGetSymbolAddress((void**)&p.xn, d_xn);
    cudaGetSymbolAddress((void**)&p.At, d_At);
    cudaGetSymbolAddress((void**)&p.Wt, d_Wt);
    cudaGetSymbolAddress((void**)&p.uA, d_uA);
    cudaGetSymbolAddress((void**)&p.vA, d_vA);
    cudaGetSymbolAddress((void**)&p.uB, d_uB);
    cudaGetSymbolAddress((void**)&p.vB, d_vB);
    cudaGetSymbolAddress((void**)&p.accA, d_accA);
    cudaGetSymbolAddress((void**)&p.accB, d_accB);
    cudaGetSymbolAddress((void**)&p.salA, d_salA);
    cudaGetSymbolAddress((void**)&p.salB, d_salB);
    cudaGetSymbolAddress((void**)&p.h, d_h);
    cudaGetSymbolAddress((void**)&p.ent, d_ent);
    cudaGetSymbolAddress((void**)&p.wA, d_wA);
    cudaGetSymbolAddress((void**)&p.wB, d_wB);
    cudaGetSymbolAddress((void**)&p.psc, d_psc);
    cudaGetSymbolAddress((void**)&p.paw, d_paw);
    cudaGetSymbolAddress((void**)&p.ebS, d_ebS);
    cudaGetSymbolAddress((void**)&p.alphaS, d_alphaS);
    cudaGetSymbolAddress((void**)&p.denA, d_denA);
    cudaGetSymbolAddress((void**)&p.denB, d_denB);
    cudaGetSymbolAddress((void**)&p.counts, d_counts);
    cudaGetSymbolAddress((void**)&p.cur, d_cur);
    cudaGetSymbolAddress((void**)&p.offs, d_offs);
    cudaGetSymbolAddress((void**)&p.csum, d_csum);
    cudaGetSymbolAddress((void**)&p.posA, d_posA);
    cudaGetSymbolAddress((void**)&p.posB, d_posB);
    cudaGetSymbolAddress((void**)&p.edge2, d_edge2);
}

// Runs everything for one layer up to (but excluding) the combine epilogue.
static void run_layer_core(const Ptrs& p,
                           const float* A, int K, int ldw,
                           const float* Wi, const float* bi, const float* ai,
                           const float* Wo, const float* bo, const float* ao,
                           const float* g,
                           const int* rowp, const int* colp, const int* et)
{
    transpose_A<<<dim3((NN + 31) / 32, 4), dim3(32, 8)>>>(A, NN, K, p.At);
    prep_wt<<<dim3(128, 4), 128>>>(Wi, Wo, ldw, K, p.Wt);
    cudaMemsetAsync(p.psc, 0, NN * 8 * sizeof(float));
    dim3 gg((NN + 127) / 128, 4);
    gemm4<<<gg, 256>>>(p.At, NN, K, p.Wt, ai, ao,
                       p.uA, p.vA, p.uB, p.vB, p.psc);
    dim3 gr(RR, 2);
    relproj2<<<gr, 128>>>(g, Wi, bi, ai, Wo, bo, ao, ldw, 2 * K,
                          p.wA, p.wB, p.paw);
    cudaMemsetAsync(p.denA, 0, NN * 2 * sizeof(float));
    cudaMemsetAsync(p.denB, 0, NN * 2 * sizeof(float));
    pass_a2<<<(EE + 255) / 256, 256>>>(rowp, colp, et, p.posA, p.posB,
                                       p.psc, p.paw, p.ebS, p.denA, p.denB);
    alpha_k<<<(2 * EE + 255) / 256, 256>>>(p.edge2, p.ebS, p.denA, p.denB, p.alphaS);
    dim3 gb((NN + 7) / 8, 2);
    pass_b_csr<<<gb, 256>>>(p.edge2, p.alphaS, p.offs, p.counts,
                            p.uA, p.wA, p.accA, p.salA,
                            p.uB, p.wB, p.accB, p.salB);
}
}  // namespace

extern "C" void kernel_launch(void* const* d_in, const int* in_sizes, int n_in,
                              void* d_out, int out_size)
{
    const float* x   = (const float*)d_in[0];
    const float* g   = (const float*)d_in[1];
    const int*   ei  = (const int*)d_in[2];
    const int*   et  = (const int*)d_in[3];
    const float* W1i = (const float*)d_in[4];
    const float* b1i = (const float*)d_in[5];
    const float* a1i = (const float*)d_in[6];
    const float* W1o = (const float*)d_in[7];
    const float* b1o = (const float*)d_in[8];
    const float* a1o = (const float*)d_in[9];
    const float* W2i = (const float*)d_in[10];
    const float* b2i = (const float*)d_in[11];
    const float* a2i = (const float*)d_in[12];
    const float* W2o = (const float*)d_in[13];
    const float* b2o = (const float*)d_in[14];
    const float* a2o = (const float*)d_in[15];
    const float* We  = (const float*)d_in[16];
    const float* be  = (const float*)d_in[17];
    const float* Wr  = (const float*)d_in[18];
    const float* br  = (const float*)d_in[19];
    float* out = (float*)d_out;

    const int* rowp = ei;
    const int* colp = ei + EE;

    Ptrs p;
    get_ptrs(p);

    // edge counting sort (once per call; shared by both layers & directions)
    const int M2 = 2 * NN;
    const int NB = (M2 + 511) / 512;
    cudaMemsetAsync(p.counts, 0, M2 * sizeof(int));
    cudaMemsetAsync(p.cur, 0, M2 * sizeof(int));
    hist_k<<<(EE + 255) / 256, 256>>>(rowp, colp, p.counts);
    scan1<<<NB, 512>>>(p.counts, p.offs, p.csum, M2);
    scan2<<<1, 256>>>(p.csum, NB);
    scan3<<<(M2 + 255) / 256, 256>>>(p.offs, p.csum, M2);
    scatter_k<<<(EE + 255) / 256, 256>>>(rowp, colp, et, p.offs, p.cur,
                                         p.edge2, p.posA, p.posB);

    norm_x<<<NN, 128>>>(x, p.xn);

    // entity layer early (depends only on xn)
    dim3 ge((NN + 63) / 64, 1);
    gemm_wt<<<ge, 256>>>(p.xn, XS, We, XS, XS, be, p.ent, 64, NN);

    // layer 1: input xn [NN,100]
    run_layer_core(p, p.xn, XS, 2 * XS + GS,
                   W1i, b1i, a1i, W1o, b1o, a1o, g, rowp, colp, et);
    combine<<<NN, 128>>>(p.accA, p.salA, p.vA, p.accB, p.salB, p.vB, p.h);

    // layer 2: input h [NN,128]; epilogue fused with entity add + final norm
    run_layer_core(p, p.h, 128, 2 * 128 + GS,
                   W2i, b2i, a2i, W2o, b2o, a2o, g, rowp, colp, et);
    combine_final<<<NN, 128>>>(p.accA, p.salA, p.vA, p.accB, p.salB, p.vB,
                               p.ent, out);

    // g_prime -> out[NN*128 : NN*128 + RR*128)
    relproj_out<<<RR, 128>>>(g, Wr, br, out + NN * 128);
}